// round 11
// baseline (speedup 1.0000x reference)
#include <cuda_runtime.h>
#include <cuda_bf16.h>
#include <stdint.h>
#include <math.h>

#define N 4096
#define NWORDS 128   // N/32
#define LOG2E 1.44269504088896f

// ---------------- device scratch ----------------
__device__ float    g_H[N * 512];
__device__ __align__(16) __nv_bfloat16 g_Hhi[N * 512];
__device__ __align__(16) __nv_bfloat16 g_Hlo[N * 512];
__device__ float    g_bufA[N * 512];
__device__ float    g_bufB[N * 512];
__device__ float    g_src[N];
__device__ float    g_tgt[N];
__device__ unsigned g_tmaxu[8];
__device__ unsigned g_adj[N * NWORDS];

// ---------------- helpers ----------------
__device__ __forceinline__ uint32_t smem_u32(const void* p) {
    uint32_t a;
    asm("{ .reg .u64 t; cvta.to.shared.u64 t, %1; cvt.u32.u64 %0, t; }" : "=r"(a) : "l"(p));
    return a;
}
__device__ __forceinline__ float ex2f(float x) {
    float y; asm("ex2.approx.ftz.f32 %0, %1;" : "=f"(y) : "f"(x)); return y;
}
__device__ __forceinline__ uint32_t packbf(float a, float b) {
    __nv_bfloat162 h = __floats2bfloat162_rn(a, b);
    return *(uint32_t*)&h;
}
__device__ __forceinline__ void cp_async16(uint32_t dst, const void* src) {
    asm volatile("cp.async.cg.shared.global [%0], [%1], 16;" :: "r"(dst), "l"(src) : "memory");
}
#define CP_COMMIT()  asm volatile("cp.async.commit_group;" ::: "memory")
#define CP_WAIT1()   asm volatile("cp.async.wait_group 1;" ::: "memory")
__device__ __forceinline__ void ldsm4t(uint32_t& r0, uint32_t& r1, uint32_t& r2, uint32_t& r3,
                                       uint32_t addr) {
    asm volatile("ldmatrix.sync.aligned.m8n8.x4.trans.shared.b16 {%0,%1,%2,%3}, [%4];"
                 : "=r"(r0), "=r"(r1), "=r"(r2), "=r"(r3) : "r"(addr));
}
__device__ __forceinline__ void mma16816(float* c, uint32_t a0, uint32_t a1, uint32_t a2,
                                         uint32_t a3, uint32_t b0, uint32_t b1) {
    asm volatile("mma.sync.aligned.m16n8k16.row.col.f32.bf16.bf16.f32 "
                 "{%0,%1,%2,%3}, {%4,%5,%6,%7}, {%8,%9}, {%0,%1,%2,%3};"
                 : "+f"(c[0]), "+f"(c[1]), "+f"(c[2]), "+f"(c[3])
                 : "r"(a0), "r"(a1), "r"(a2), "r"(a3), "r"(b0), "r"(b1));
}
// p = adj ? exp2(lrelu(src+t)*log2e - mscaled) : 0
__device__ __forceinline__ float pv(float src, float mscaled, float t, unsigned aw, int sh) {
    float l = src + t;
    l = fmaxf(l, 0.2f * l);
    float arg = fmaf(l, LOG2E, -mscaled);
    arg = ((aw >> sh) & 1u) ? arg : -1e30f;
    return ex2f(arg);
}

// ---------------- adj int32 -> bitmask (+ tmax slot reset) ----------------
__global__ void pack_adj(const int* __restrict__ adj) {
    int idx = blockIdx.x * blockDim.x + threadIdx.x;
    if (blockIdx.x == 0 && threadIdx.x < 8) g_tmaxu[threadIdx.x] = 0u;
    unsigned b = __ballot_sync(0xffffffffu, adj[idx] > 0);
    if ((threadIdx.x & 31) == 0) g_adj[idx >> 5] = b;
}

// ---------------- tiled fp32 GEMM (features) + fused bf16 hi/lo split ----------------
template<int BM, int BN, int BK, int TM, int TN>
__global__ __launch_bounds__((BM/TM)*(BN/TN))
void sgemm(const float* __restrict__ A, const float* __restrict__ B,
           float* __restrict__ C, int M, int Nn, int K,
           __nv_bfloat16* __restrict__ Hhi, __nv_bfloat16* __restrict__ Hlo)
{
    constexpr int THREADS = (BM/TM)*(BN/TN);
    __shared__ float As[BK][BM + 1];
    __shared__ __align__(16) float Bs[BK][BN];
    int tid  = threadIdx.x;
    int row0 = blockIdx.y * BM, col0 = blockIdx.x * BN;
    int tx   = tid % (BN/TN), ty = tid / (BN/TN);
    float acc[TM][TN] = {};
    for (int k0 = 0; k0 < K; k0 += BK) {
        __syncthreads();
        for (int i = tid; i < BM*BK; i += THREADS) {
            int m = i / BK, k = i % BK;
            As[k][m] = A[(size_t)(row0 + m) * K + k0 + k];
        }
        for (int i = tid; i < BK*BN; i += THREADS) {
            int k = i / BN, n = i % BN;
            Bs[k][n] = B[(size_t)(k0 + k) * Nn + col0 + n];
        }
        __syncthreads();
        #pragma unroll 4
        for (int kk = 0; kk < BK; kk++) {
            float af[TM], bf[TN];
            #pragma unroll
            for (int m = 0; m < TM; m++) af[m] = As[kk][ty*TM + m];
            #pragma unroll
            for (int n = 0; n < TN; n++) bf[n] = Bs[kk][tx*TN + n];
            #pragma unroll
            for (int m = 0; m < TM; m++)
                #pragma unroll
                for (int n = 0; n < TN; n++) acc[m][n] += af[m] * bf[n];
        }
    }
    #pragma unroll
    for (int m = 0; m < TM; m++) {
        size_t base = (size_t)(row0 + ty*TM + m) * Nn + col0 + tx*TN;
        #pragma unroll
        for (int n = 0; n < TN; n++) {
            float v = acc[m][n];
            C[base + n] = v;
            __nv_bfloat16 h = __float2bfloat16_rn(v);
            Hhi[base + n] = h;
            Hlo[base + n] = __float2bfloat16_rn(v - __bfloat162float(h));
        }
    }
}

// ---------------- src/tgt + fused global tgt-max ----------------
__global__ void src_tgt(const float* __restrict__ H, const float* __restrict__ a,
                        int fo, int layer)
{
    __shared__ unsigned keys[8];
    int wid  = threadIdx.x >> 5;
    int row  = blockIdx.x * (blockDim.x / 32) + wid;
    int lane = threadIdx.x & 31;
    float s = 0.f, t = 0.f;
    for (int c = lane; c < fo; c += 32) {
        float h = H[(size_t)row * fo + c];
        s += h * a[c];
        t += h * a[fo + c];
    }
    #pragma unroll
    for (int o = 16; o; o >>= 1) {
        s += __shfl_xor_sync(0xffffffffu, s, o);
        t += __shfl_xor_sync(0xffffffffu, t, o);
    }
    if (!lane) {
        g_src[row] = s; g_tgt[row] = t;
        unsigned b = __float_as_uint(t);
        keys[wid] = (b & 0x80000000u) ? ~b : (b | 0x80000000u);
    }
    __syncthreads();
    if (threadIdx.x == 0) {
        unsigned k = keys[0];
        #pragma unroll
        for (int i = 1; i < 8; i++) k = max(k, keys[i]);
        atomicMax(&g_tmaxu[layer], k);
    }
}

// ---------------- HMMA fused attention (3-stream split, cp.async x3, 1 sync/stage) ----------------
// streams: Phi*Hhi + Phi*Hlo + Plo*Hhi  (residual = Plo*Hlo ~ 1.6e-5)
template<int NMMA, int RW, int CW>
__global__ __launch_bounds__(256)
void attn_mma(const __nv_bfloat16* __restrict__ Hhi, const __nv_bfloat16* __restrict__ Hlo,
              float* __restrict__ OUT, int fo, int layer)
{
    constexpr int ROWS  = 16 * RW;
    constexpr int NW    = NMMA / CW;
    constexpr int NCP   = (NW + 15) / 16;
    constexpr int LDH   = NMMA + 8;
    constexpr int CH    = 64 * NMMA / 8;        // 16B chunks per array per stage
    constexpr int BUFE  = 64 * LDH;             // bf16 elems per (hi|lo) tile
    constexpr int BUFE2 = 2 * BUFE;             // hi+lo

    extern __shared__ __align__(16) char sm[];
    __nv_bfloat16* HsB = (__nv_bfloat16*)sm;    // 3 x [hi tile | lo tile]

    int tid = threadIdx.x, lane = tid & 31, wid = tid >> 5;
    int warpR = wid / CW, warpC = wid % CW;
    int row0 = blockIdx.y * ROWS;
    int col0 = blockIdx.x * NMMA;
    int q = lane & 3;

    unsigned tu = g_tmaxu[layer];
    unsigned fb = (tu & 0x80000000u) ? (tu & 0x7fffffffu) : ~tu;
    float tmax = __uint_as_float(fb);

    int r0 = row0 + warpR * 16 + (lane >> 2);
    int r1 = r0 + 8;
    float s0 = g_src[r0], s1 = g_src[r1];
    float lm0 = s0 + tmax, lm1 = s1 + tmax;
    float m0 = fmaxf(lm0, 0.2f * lm0) * LOG2E;
    float m1 = fmaxf(lm1, 0.2f * lm1) * LOG2E;
    const unsigned* a0p = g_adj + (size_t)r0 * NWORDS;
    const unsigned* a1p = g_adj + (size_t)r1 * NWORDS;
    float z0 = 0.f, z1 = 0.f;

    float acc[NCP][8] = {};

    uint32_t lrow = lane & 15, lc8 = (lane >> 4) * 8;

    auto issue = [&](int s) {
        if (s < 64) {
            int buf = s % 3;
            const __nv_bfloat16* gHi = Hhi + (size_t)(s * 64) * fo + col0;
            const __nv_bfloat16* gLo = Hlo + (size_t)(s * 64) * fo + col0;
            #pragma unroll
            for (int i = 0; i < 2 * CH; i += 256) {
                int idx = i + tid;
                if ((2 * CH % 256 == 0) || idx < 2 * CH) {
                    int lo = idx >= CH;
                    int r  = lo ? idx - CH : idx;
                    int k  = r / (NMMA / 8), c = r % (NMMA / 8);
                    uint32_t dst = smem_u32(HsB + buf * BUFE2 + lo * BUFE + k * LDH + c * 8);
                    const __nv_bfloat16* src = (lo ? gLo : gHi) + (size_t)k * fo + c * 8;
                    cp_async16(dst, src);
                }
            }
        }
        CP_COMMIT();
    };

    issue(0); issue(1);

    for (int st = 0; st < 64; st++) {
        int buf = st % 3;
        unsigned w00 = a0p[st * 2], w01 = a0p[st * 2 + 1];
        unsigned w10 = a1p[st * 2], w11 = a1p[st * 2 + 1];

        CP_WAIT1();
        __syncthreads();          // buf st ready for all; compute st-1 retired
        issue(st + 2);            // overwrites buf (st-1)%3 — safe after barrier

        uint32_t bHi = smem_u32(HsB + buf * BUFE2 + lrow * LDH + warpC * NW + lc8);
        uint32_t bLo = bHi + (uint32_t)(BUFE * 2);

        #pragma unroll
        for (int ks = 0; ks < 4; ks++) {
            unsigned aw0 = (ks < 2) ? w00 : w01;
            unsigned aw1 = (ks < 2) ? w10 : w11;
            int sh = ((ks & 1) << 4) + 2 * q;
            int kl = st * 64 + ks * 16 + 2 * q;
            float t0 = __ldg(&g_tgt[kl]),     t1 = __ldg(&g_tgt[kl + 1]);
            float t8 = __ldg(&g_tgt[kl + 8]), t9 = __ldg(&g_tgt[kl + 9]);

            float p00 = pv(s0, m0, t0, aw0, sh),     p01 = pv(s0, m0, t1, aw0, sh + 1);
            float p08 = pv(s0, m0, t8, aw0, sh + 8), p09 = pv(s0, m0, t9, aw0, sh + 9);
            float p10 = pv(s1, m1, t0, aw1, sh),     p11 = pv(s1, m1, t1, aw1, sh + 1);
            float p18 = pv(s1, m1, t8, aw1, sh + 8), p19 = pv(s1, m1, t9, aw1, sh + 9);
            z0 += (p00 + p01) + (p08 + p09);
            z1 += (p10 + p11) + (p18 + p19);

            uint32_t ah0 = packbf(p00, p01), ah1 = packbf(p10, p11);
            uint32_t ah2 = packbf(p08, p09), ah3 = packbf(p18, p19);
            __nv_bfloat162 v0 = *(__nv_bfloat162*)&ah0, v1 = *(__nv_bfloat162*)&ah1;
            __nv_bfloat162 v2 = *(__nv_bfloat162*)&ah2, v3 = *(__nv_bfloat162*)&ah3;
            uint32_t al0 = packbf(p00 - __bfloat162float(v0.x), p01 - __bfloat162float(v0.y));
            uint32_t al1 = packbf(p10 - __bfloat162float(v1.x), p11 - __bfloat162float(v1.y));
            uint32_t al2 = packbf(p08 - __bfloat162float(v2.x), p09 - __bfloat162float(v2.y));
            uint32_t al3 = packbf(p18 - __bfloat162float(v3.x), p19 - __bfloat162float(v3.y));

            uint32_t rowoff = (uint32_t)(ks * 16 * LDH * 2);
            #pragma unroll
            for (int cp = 0; cp < NCP; cp++) {
                uint32_t off = rowoff + (uint32_t)(cp * 32);
                uint32_t h0, h1, h2, h3, L0, L1, L2, L3;
                ldsm4t(h0, h1, h2, h3, bHi + off);
                ldsm4t(L0, L1, L2, L3, bLo + off);
                mma16816(acc[cp],     ah0, ah1, ah2, ah3, h0, h1);
                mma16816(acc[cp],     ah0, ah1, ah2, ah3, L0, L1);
                mma16816(acc[cp],     al0, al1, al2, al3, h0, h1);
                mma16816(acc[cp] + 4, ah0, ah1, ah2, ah3, h2, h3);
                mma16816(acc[cp] + 4, ah0, ah1, ah2, ah3, L2, L3);
                mma16816(acc[cp] + 4, al0, al1, al2, al3, h2, h3);
            }
        }
    }

    z0 += __shfl_xor_sync(0xffffffffu, z0, 1);
    z0 += __shfl_xor_sync(0xffffffffu, z0, 2);
    z1 += __shfl_xor_sync(0xffffffffu, z1, 1);
    z1 += __shfl_xor_sync(0xffffffffu, z1, 2);
    float iz0 = 1.f / z0, iz1 = 1.f / z1;

    #pragma unroll
    for (int cp = 0; cp < NCP; cp++) {
        #pragma unroll
        for (int c = 0; c < 2; c++) {
            if (cp * 16 + c * 8 < NW) {
                int ncol = col0 + warpC * NW + cp * 16 + c * 8 + 2 * q;
                float2 o0, o1;
                o0.x = acc[cp][c * 4 + 0] * iz0; o0.y = acc[cp][c * 4 + 1] * iz0;
                o1.x = acc[cp][c * 4 + 2] * iz1; o1.y = acc[cp][c * 4 + 3] * iz1;
                *(float2*)(OUT + (size_t)r0 * fo + ncol) = o0;
                *(float2*)(OUT + (size_t)r1 * fo + ncol) = o1;
            }
        }
    }
}

// ---------------- orchestration ----------------
static int smem_attn(int nm) { return 3 * 2 * 64 * (nm + 8) * 2; }

extern "C" void kernel_launch(void* const* d_in, const int* in_sizes, int n_in,
                              void* d_out, int out_size)
{
    const float* x   = (const float*)d_in[0];
    const int*   adj = (const int*)d_in[1];
    const float* w[8]; const float* a[8];
    for (int i = 0; i < 8; i++) {
        w[i] = (const float*)d_in[2 + 2*i];
        a[i] = (const float*)d_in[3 + 2*i];
    }
    float* out = (float*)d_out;

    float *H, *bufA, *bufB;
    __nv_bfloat16 *Hhi, *Hlo;
    cudaGetSymbolAddress((void**)&H,    g_H);
    cudaGetSymbolAddress((void**)&Hhi,  g_Hhi);
    cudaGetSymbolAddress((void**)&Hlo,  g_Hlo);
    cudaGetSymbolAddress((void**)&bufA, g_bufA);
    cudaGetSymbolAddress((void**)&bufB, g_bufB);

    static bool attr_set = false;
    if (!attr_set) {
        cudaFuncSetAttribute(attn_mma<128, 8, 1>, cudaFuncAttributeMaxDynamicSharedMemorySize, smem_attn(128));
        cudaFuncSetAttribute(attn_mma<128, 4, 2>, cudaFuncAttributeMaxDynamicSharedMemorySize, smem_attn(128));
        cudaFuncSetAttribute(attn_mma<128, 2, 4>, cudaFuncAttributeMaxDynamicSharedMemorySize, smem_attn(128));
        cudaFuncSetAttribute(attn_mma<64, 2, 4>,  cudaFuncAttributeMaxDynamicSharedMemorySize, smem_attn(64));
        cudaFuncSetAttribute(attn_mma<16, 4, 2>,  cudaFuncAttributeMaxDynamicSharedMemorySize, smem_attn(16));
        attr_set = true;
    }

    const size_t OFF_H1 = (size_t)N * 512;
    const size_t OFF_H2 = OFF_H1 + (size_t)N * 256;
    const size_t OFF_H3 = OFF_H2 + (size_t)N * 128;
    const size_t OFF_H4 = OFF_H3 + (size_t)N * 64;

    pack_adj<<<(size_t)N * N / 256, 256>>>(adj);

    const int FI[8] = {512, 256, 128, 64, 16,  64, 128, 256};
    const int FO[8] = {256, 128,  64, 16, 64, 128, 256, 512};
    float* outs[8] = { out + OFF_H1, out + OFF_H2, out + OFF_H3, out + OFF_H4,
                       bufA, bufB, bufA, out };
    const float* ins[8];
    ins[0] = x;
    for (int l = 1; l < 8; l++) ins[l] = outs[l - 1];

    for (int l = 0; l < 8; l++) {
        int fi = FI[l], fo = FO[l];

        if (fo >= 64)
            sgemm<128, 64, 16, 8, 4><<<dim3(fo / 64, N / 128), 256>>>(ins[l], w[l], H, N, fo, fi, Hhi, Hlo);
        else
            sgemm<64, 16, 16, 4, 1><<<dim3(1, N / 64), 256>>>(ins[l], w[l], H, N, fo, fi, Hhi, Hlo);

        src_tgt<<<N / 8, 256>>>(H, a[l], fo, l);

        switch (fo) {
            case 512:
                attn_mma<128, 8, 1><<<dim3(4, N / 128), 256, smem_attn(128)>>>(Hhi, Hlo, outs[l], fo, l); break;
            case 256:
                attn_mma<128, 4, 2><<<dim3(2, N / 64), 256, smem_attn(128)>>>(Hhi, Hlo, outs[l], fo, l); break;
            case 128:
                attn_mma<128, 2, 4><<<dim3(1, N / 32), 256, smem_attn(128)>>>(Hhi, Hlo, outs[l], fo, l); break;
            case 64:
                attn_mma<64, 2, 4><<<dim3(1, N / 32), 256, smem_attn(64)>>>(Hhi, Hlo, outs[l], fo, l); break;
            case 16:
                attn_mma<16, 4, 2><<<dim3(1, N / 64), 256, smem_attn(16)>>>(Hhi, Hlo, outs[l], fo, l); break;
        }
    }
    (void)in_sizes; (void)n_in; (void)out_size;
}

// round 12
// speedup vs baseline: 1.3004x; 1.3004x over previous
#include <cuda_runtime.h>
#include <cuda_bf16.h>
#include <stdint.h>
#include <math.h>

#define N 4096
#define NWORDS 128   // N/32
#define LOG2E 1.44269504088896f

// ---------------- device scratch ----------------
__device__ float    g_H[N * 512];
__device__ __align__(16) __nv_bfloat16 g_Hhi[N * 512];
__device__ __align__(16) __nv_bfloat16 g_Hlo[N * 512];
__device__ float    g_bufA[N * 512];
__device__ float    g_bufB[N * 512];
__device__ float    g_src[N];
__device__ float    g_tgt[N];
__device__ unsigned g_tmaxu[8];
__device__ unsigned g_adj[N * NWORDS];
__device__ __align__(16) float4 g_E[N];   // {E1, E2, theta, pad} per row
__device__ __align__(16) float2 g_F[N];   // {F1, F2} per col

// ---------------- helpers ----------------
__device__ __forceinline__ uint32_t smem_u32(const void* p) {
    uint32_t a;
    asm("{ .reg .u64 t; cvta.to.shared.u64 t, %1; cvt.u32.u64 %0, t; }" : "=r"(a) : "l"(p));
    return a;
}
__device__ __forceinline__ float ex2f(float x) {
    float y; asm("ex2.approx.ftz.f32 %0, %1;" : "=f"(y) : "f"(x)); return y;
}
__device__ __forceinline__ uint32_t packbf(float a, float b) {
    __nv_bfloat162 h = __floats2bfloat162_rn(a, b);
    return *(uint32_t*)&h;
}
__device__ __forceinline__ void cp_async16(uint32_t dst, const void* src) {
    asm volatile("cp.async.cg.shared.global [%0], [%1], 16;" :: "r"(dst), "l"(src) : "memory");
}
#define CP_COMMIT()  asm volatile("cp.async.commit_group;" ::: "memory")
#define CP_WAIT0()   asm volatile("cp.async.wait_group 0;" ::: "memory")
__device__ __forceinline__ void ldsm4t(uint32_t& r0, uint32_t& r1, uint32_t& r2, uint32_t& r3,
                                       uint32_t addr) {
    asm volatile("ldmatrix.sync.aligned.m8n8.x4.trans.shared.b16 {%0,%1,%2,%3}, [%4];"
                 : "=r"(r0), "=r"(r1), "=r"(r2), "=r"(r3) : "r"(addr));
}
__device__ __forceinline__ void mma16816(float* c, uint32_t a0, uint32_t a1, uint32_t a2,
                                         uint32_t a3, uint32_t b0, uint32_t b1) {
    asm volatile("mma.sync.aligned.m16n8k16.row.col.f32.bf16.bf16.f32 "
                 "{%0,%1,%2,%3}, {%4,%5,%6,%7}, {%8,%9}, {%0,%1,%2,%3};"
                 : "+f"(c[0]), "+f"(c[1]), "+f"(c[2]), "+f"(c[3])
                 : "r"(a0), "r"(a1), "r"(a2), "r"(a3), "r"(b0), "r"(b1));
}
// separable softmax numerator: no exp in the hot loop
__device__ __forceinline__ float pcalc(float4 e, float2 f, unsigned aw, int sh) {
    bool br = f.x > e.z;               // F1 > theta  <=>  s_i + t_j > 0
    float E = br ? e.x : e.y;
    float F = br ? f.x : f.y;
    float p = E * F;
    return ((aw >> sh) & 1u) ? p : 0.f;
}

// ---------------- adj int32 -> bitmask (+ tmax slot reset) ----------------
__global__ void pack_adj(const int* __restrict__ adj) {
    int idx = blockIdx.x * blockDim.x + threadIdx.x;
    if (blockIdx.x == 0 && threadIdx.x < 8) g_tmaxu[threadIdx.x] = 0u;
    unsigned b = __ballot_sync(0xffffffffu, adj[idx] > 0);
    if ((threadIdx.x & 31) == 0) g_adj[idx >> 5] = b;
}

// ---------------- tiled fp32 GEMM (features) + fused bf16 hi/lo split ----------------
template<int BM, int BN, int BK, int TM, int TN>
__global__ __launch_bounds__((BM/TM)*(BN/TN))
void sgemm(const float* __restrict__ A, const float* __restrict__ B,
           float* __restrict__ C, int M, int Nn, int K,
           __nv_bfloat16* __restrict__ Hhi, __nv_bfloat16* __restrict__ Hlo)
{
    constexpr int THREADS = (BM/TM)*(BN/TN);
    __shared__ float As[BK][BM + 1];
    __shared__ __align__(16) float Bs[BK][BN];
    int tid  = threadIdx.x;
    int row0 = blockIdx.y * BM, col0 = blockIdx.x * BN;
    int tx   = tid % (BN/TN), ty = tid / (BN/TN);
    float acc[TM][TN] = {};
    for (int k0 = 0; k0 < K; k0 += BK) {
        __syncthreads();
        for (int i = tid; i < BM*BK; i += THREADS) {
            int m = i / BK, k = i % BK;
            As[k][m] = A[(size_t)(row0 + m) * K + k0 + k];
        }
        for (int i = tid; i < BK*BN; i += THREADS) {
            int k = i / BN, n = i % BN;
            Bs[k][n] = B[(size_t)(k0 + k) * Nn + col0 + n];
        }
        __syncthreads();
        #pragma unroll 4
        for (int kk = 0; kk < BK; kk++) {
            float af[TM], bf[TN];
            #pragma unroll
            for (int m = 0; m < TM; m++) af[m] = As[kk][ty*TM + m];
            #pragma unroll
            for (int n = 0; n < TN; n++) bf[n] = Bs[kk][tx*TN + n];
            #pragma unroll
            for (int m = 0; m < TM; m++)
                #pragma unroll
                for (int n = 0; n < TN; n++) acc[m][n] += af[m] * bf[n];
        }
    }
    #pragma unroll
    for (int m = 0; m < TM; m++) {
        size_t base = (size_t)(row0 + ty*TM + m) * Nn + col0 + tx*TN;
        #pragma unroll
        for (int n = 0; n < TN; n++) {
            float v = acc[m][n];
            C[base + n] = v;
            __nv_bfloat16 h = __float2bfloat16_rn(v);
            Hhi[base + n] = h;
            Hlo[base + n] = __float2bfloat16_rn(v - __bfloat162float(h));
        }
    }
}

// ---------------- src/tgt + fused global tgt-max ----------------
__global__ void src_tgt(const float* __restrict__ H, const float* __restrict__ a,
                        int fo, int layer)
{
    __shared__ unsigned keys[8];
    int wid  = threadIdx.x >> 5;
    int row  = blockIdx.x * (blockDim.x / 32) + wid;
    int lane = threadIdx.x & 31;
    float s = 0.f, t = 0.f;
    for (int c = lane; c < fo; c += 32) {
        float h = H[(size_t)row * fo + c];
        s += h * a[c];
        t += h * a[fo + c];
    }
    #pragma unroll
    for (int o = 16; o; o >>= 1) {
        s += __shfl_xor_sync(0xffffffffu, s, o);
        t += __shfl_xor_sync(0xffffffffu, t, o);
    }
    if (!lane) {
        g_src[row] = s; g_tgt[row] = t;
        unsigned b = __float_as_uint(t);
        keys[wid] = (b & 0x80000000u) ? ~b : (b | 0x80000000u);
    }
    __syncthreads();
    if (threadIdx.x == 0) {
        unsigned k = keys[0];
        #pragma unroll
        for (int i = 1; i < 8; i++) k = max(k, keys[i]);
        atomicMax(&g_tmaxu[layer], k);
    }
}

// ---------------- per-layer E/F factor tables (16K exps total) ----------------
__global__ void ef_k(int layer)
{
    int i = blockIdx.x * 256 + threadIdx.x;
    unsigned tu = g_tmaxu[layer];
    unsigned fb = (tu & 0x80000000u) ? (tu & 0x7fffffffu) : ~tu;
    float tmax = __uint_as_float(fb);
    float s = g_src[i], t = g_tgt[i];
    float sp = s + tmax;
    float m  = fmaxf(sp, 0.2f * sp);                 // row max (exact, global tmax)
    float E1 = ex2f((sp - m) * LOG2E);               // <= 1
    float E2 = ex2f((0.2f * sp - m) * LOG2E);        // <= 1
    float th = ex2f((-sp) * LOG2E);                  // theta; sat to inf/0 is safe
    float F1 = ex2f((t - tmax) * LOG2E);             // <= 1
    float F2 = ex2f(0.2f * (t - tmax) * LOG2E);      // <= 1
    g_E[i] = make_float4(E1, E2, th, 0.f);
    g_F[i] = make_float2(F1, F2);
}

// ---------------- HMMA fused attention ----------------
// 8 warps = 2 row-groups x 4 k-groups. Each warp: 16 rows x full NMMA cols x its
// 16-k chunk per stage -> zero P duplication. 3 MMA streams: Phi*Hhi + Phi*Hlo + Plo*Hhi.
// 2-stage cp.async pipeline; F1/F2 in smem; final cross-kw tree reduce in smem.
template<int NMMA>
__global__ __launch_bounds__(256, 2)
void attn_sep(const __nv_bfloat16* __restrict__ Hhi, const __nv_bfloat16* __restrict__ Hlo,
              float* __restrict__ OUT, int fo)
{
    constexpr int ROWS    = 32;
    constexpr int NCP     = NMMA / 16;
    constexpr int LDH     = NMMA + 8;
    constexpr int STAGE_E = 64 * LDH;          // bf16 elems per plane per stage
    constexpr int CHP     = 64 * NMMA / 8;     // 16B chunks per plane per stage
    constexpr int RSTR    = NCP * 8 + 1;       // redbuf lane stride (odd -> conflict-free)

    extern __shared__ __align__(16) char sm[];
    __nv_bfloat16* Ht = (__nv_bfloat16*)sm;                       // [2 stages][2 planes][64][LDH]
    float2* FF  = (float2*)(sm + 4 * STAGE_E * 2);                // 4096 x {F1,F2} = 32KB
    float* zrow = (float*)(sm + 4 * STAGE_E * 2 + 32768);         // [ROWS]
    float* redbuf = (float*)sm;                                   // alias Ht after main loop

    int tid = threadIdx.x, lane = tid & 31, wid = tid >> 5;
    int warpR = wid & 1, kw = wid >> 1;
    int row0 = blockIdx.y * ROWS, col0 = blockIdx.x * NMMA;
    int q = lane & 3;

    int r0 = row0 + warpR * 16 + (lane >> 2), r1 = r0 + 8;
    float4 e0 = g_E[r0], e1 = g_E[r1];
    const unsigned* a0p = g_adj + (size_t)r0 * NWORDS;
    const unsigned* a1p = g_adj + (size_t)r1 * NWORDS;
    float z0 = 0.f, z1 = 0.f;
    float acc[NCP][8] = {};

    if (tid < ROWS) zrow[tid] = 0.f;
    {   // preload F table (32KB) to smem
        const float4* gf = (const float4*)g_F;
        float4* sf = (float4*)FF;
        for (int idx = tid; idx < N / 2; idx += 256) sf[idx] = gf[idx];
    }

    auto issue = [&](int s) {
        if (s < 64) {
            int buf = s & 1;
            const __nv_bfloat16* gHi = Hhi + (size_t)(s * 64) * fo + col0;
            const __nv_bfloat16* gLo = Hlo + (size_t)(s * 64) * fo + col0;
            #pragma unroll
            for (int i = 0; i < 2 * CHP; i += 256) {
                int idx = i + tid;
                int pl = idx >= CHP;
                int r  = pl ? idx - CHP : idx;
                int k  = r / (NMMA / 8), c = r % (NMMA / 8);
                uint32_t dst = smem_u32(Ht + ((size_t)(buf * 2 + pl) * 64 + k) * LDH + c * 8);
                cp_async16(dst, (pl ? gLo : gHi) + (size_t)k * fo + c * 8);
            }
        }
        CP_COMMIT();
    };

    issue(0);
    __syncthreads();    // FF + zrow visible

    for (int st = 0; st < 64; st++) {
        int buf = st & 1;
        // ---- P fragments (registers; overlaps the in-flight cp.async) ----
        unsigned aw0 = a0p[st * 2 + (kw >> 1)];
        unsigned aw1 = a1p[st * 2 + (kw >> 1)];
        int sh = ((kw & 1) << 4) + 2 * q;
        int jb = st * 64 + kw * 16 + 2 * q;
        float2 f0 = FF[jb], f1 = FF[jb + 1], f8 = FF[jb + 8], f9 = FF[jb + 9];

        float p00 = pcalc(e0, f0, aw0, sh),     p01 = pcalc(e0, f1, aw0, sh + 1);
        float p08 = pcalc(e0, f8, aw0, sh + 8), p09 = pcalc(e0, f9, aw0, sh + 9);
        float p10 = pcalc(e1, f0, aw1, sh),     p11 = pcalc(e1, f1, aw1, sh + 1);
        float p18 = pcalc(e1, f8, aw1, sh + 8), p19 = pcalc(e1, f9, aw1, sh + 9);
        z0 += (p00 + p01) + (p08 + p09);
        z1 += (p10 + p11) + (p18 + p19);

        uint32_t ah0 = packbf(p00, p01), ah1 = packbf(p10, p11);
        uint32_t ah2 = packbf(p08, p09), ah3 = packbf(p18, p19);
        __nv_bfloat162 v0 = *(__nv_bfloat162*)&ah0, v1 = *(__nv_bfloat162*)&ah1;
        __nv_bfloat162 v2 = *(__nv_bfloat162*)&ah2, v3 = *(__nv_bfloat162*)&ah3;
        uint32_t al0 = packbf(p00 - __bfloat162float(v0.x), p01 - __bfloat162float(v0.y));
        uint32_t al1 = packbf(p10 - __bfloat162float(v1.x), p11 - __bfloat162float(v1.y));
        uint32_t al2 = packbf(p08 - __bfloat162float(v2.x), p09 - __bfloat162float(v2.y));
        uint32_t al3 = packbf(p18 - __bfloat162float(v3.x), p19 - __bfloat162float(v3.y));

        // ---- pipeline turn ----
        CP_WAIT0();          // stage st data (only outstanding group) arrived
        __syncthreads();     // visible to all; all warps done with MMA(st-1)
        issue(st + 1);       // prefetch next stage into the other buffer

        // ---- MMA ----
        uint32_t bHi = smem_u32(Ht + ((size_t)(buf * 2) * 64 + kw * 16 + (lane & 15)) * LDH
                                + (lane >> 4) * 8);
        uint32_t bLo = bHi + (uint32_t)(64 * LDH * 2);
        #pragma unroll
        for (int cp = 0; cp < NCP; cp++) {
            uint32_t off = (uint32_t)(cp * 32);
            uint32_t h0, h1, h2, h3, L0, L1, L2, L3;
            ldsm4t(h0, h1, h2, h3, bHi + off);
            ldsm4t(L0, L1, L2, L3, bLo + off);
            mma16816(acc[cp],     ah0, ah1, ah2, ah3, h0, h1);
            mma16816(acc[cp],     ah0, ah1, ah2, ah3, L0, L1);
            mma16816(acc[cp],     al0, al1, al2, al3, h0, h1);
            mma16816(acc[cp] + 4, ah0, ah1, ah2, ah3, h2, h3);
            mma16816(acc[cp] + 4, ah0, ah1, ah2, ah3, L2, L3);
            mma16816(acc[cp] + 4, al0, al1, al2, al3, h2, h3);
        }
    }

    // ---- Z: quad reduce + smem atomic across kw warps ----
    z0 += __shfl_xor_sync(0xffffffffu, z0, 1);
    z0 += __shfl_xor_sync(0xffffffffu, z0, 2);
    z1 += __shfl_xor_sync(0xffffffffu, z1, 1);
    z1 += __shfl_xor_sync(0xffffffffu, z1, 2);
    if (q == 0) {
        atomicAdd(&zrow[warpR * 16 + (lane >> 2)],     z0);
        atomicAdd(&zrow[warpR * 16 + 8 + (lane >> 2)], z1);
    }
    __syncthreads();   // Ht reads done -> redbuf alias safe; z atomics posted

    // ---- cross-kw accumulator tree reduce (redbuf aliases Ht) ----
    if (wid >= 4) {
        float* rb = redbuf + (wid - 4) * (32 * RSTR) + lane * RSTR;
        #pragma unroll
        for (int cp = 0; cp < NCP; cp++)
            #pragma unroll
            for (int c = 0; c < 8; c++) rb[cp * 8 + c] = acc[cp][c];
    }
    __syncthreads();
    if (wid < 4) {
        float* rb = redbuf + wid * (32 * RSTR) + lane * RSTR;
        #pragma unroll
        for (int cp = 0; cp < NCP; cp++)
            #pragma unroll
            for (int c = 0; c < 8; c++) acc[cp][c] += rb[cp * 8 + c];
    }
    __syncthreads();
    if (wid == 2 || wid == 3) {
        float* rb = redbuf + (wid - 2) * (32 * RSTR) + lane * RSTR;
        #pragma unroll
        for (int cp = 0; cp < NCP; cp++)
            #pragma unroll
            for (int c = 0; c < 8; c++) rb[cp * 8 + c] = acc[cp][c];
    }
    __syncthreads();
    if (wid < 2) {
        float* rb = redbuf + wid * (32 * RSTR) + lane * RSTR;
        #pragma unroll
        for (int cp = 0; cp < NCP; cp++)
            #pragma unroll
            for (int c = 0; c < 8; c++) acc[cp][c] += rb[cp * 8 + c];

        float iz0 = 1.f / zrow[warpR * 16 + (lane >> 2)];
        float iz1 = 1.f / zrow[warpR * 16 + 8 + (lane >> 2)];
        #pragma unroll
        for (int cp = 0; cp < NCP; cp++) {
            #pragma unroll
            for (int c = 0; c < 2; c++) {
                int ncol = col0 + cp * 16 + c * 8 + 2 * q;
                float2 o0, o1;
                o0.x = acc[cp][c * 4 + 0] * iz0; o0.y = acc[cp][c * 4 + 1] * iz0;
                o1.x = acc[cp][c * 4 + 2] * iz1; o1.y = acc[cp][c * 4 + 3] * iz1;
                *(float2*)(OUT + (size_t)r0 * fo + ncol) = o0;
                *(float2*)(OUT + (size_t)r1 * fo + ncol) = o1;
            }
        }
    }
}

// ---------------- orchestration ----------------
static int smem_attn(int nm) {
    return 4 * 64 * (nm + 8) * 2 + 32768 + 128;   // H tiles + FF + zrow
}

extern "C" void kernel_launch(void* const* d_in, const int* in_sizes, int n_in,
                              void* d_out, int out_size)
{
    const float* x   = (const float*)d_in[0];
    const int*   adj = (const int*)d_in[1];
    const float* w[8]; const float* a[8];
    for (int i = 0; i < 8; i++) {
        w[i] = (const float*)d_in[2 + 2*i];
        a[i] = (const float*)d_in[3 + 2*i];
    }
    float* out = (float*)d_out;

    float *H, *bufA, *bufB;
    __nv_bfloat16 *Hhi, *Hlo;
    cudaGetSymbolAddress((void**)&H,    g_H);
    cudaGetSymbolAddress((void**)&Hhi,  g_Hhi);
    cudaGetSymbolAddress((void**)&Hlo,  g_Hlo);
    cudaGetSymbolAddress((void**)&bufA, g_bufA);
    cudaGetSymbolAddress((void**)&bufB, g_bufB);

    static bool attr_set = false;
    if (!attr_set) {
        cudaFuncSetAttribute(attn_sep<128>, cudaFuncAttributeMaxDynamicSharedMemorySize, smem_attn(128));
        cudaFuncSetAttribute(attn_sep<64>,  cudaFuncAttributeMaxDynamicSharedMemorySize, smem_attn(64));
        cudaFuncSetAttribute(attn_sep<16>,  cudaFuncAttributeMaxDynamicSharedMemorySize, smem_attn(16));
        attr_set = true;
    }

    const size_t OFF_H1 = (size_t)N * 512;
    const size_t OFF_H2 = OFF_H1 + (size_t)N * 256;
    const size_t OFF_H3 = OFF_H2 + (size_t)N * 128;
    const size_t OFF_H4 = OFF_H3 + (size_t)N * 64;

    pack_adj<<<(size_t)N * N / 256, 256>>>(adj);

    const int FI[8] = {512, 256, 128, 64, 16,  64, 128, 256};
    const int FO[8] = {256, 128,  64, 16, 64, 128, 256, 512};
    float* outs[8] = { out + OFF_H1, out + OFF_H2, out + OFF_H3, out + OFF_H4,
                       bufA, bufB, bufA, out };
    const float* ins[8];
    ins[0] = x;
    for (int l = 1; l < 8; l++) ins[l] = outs[l - 1];

    for (int l = 0; l < 8; l++) {
        int fi = FI[l], fo = FO[l];

        if (fo >= 64)
            sgemm<128, 64, 16, 8, 4><<<dim3(fo / 64, N / 128), 256>>>(ins[l], w[l], H, N, fo, fi, Hhi, Hlo);
        else
            sgemm<64, 16, 16, 4, 1><<<dim3(1, N / 64), 256>>>(ins[l], w[l], H, N, fo, fi, Hhi, Hlo);

        src_tgt<<<N / 8, 256>>>(H, a[l], fo, l);
        ef_k<<<N / 256, 256>>>(l);

        switch (fo) {
            case 512:
                attn_sep<128><<<dim3(4, N / 32), 256, smem_attn(128)>>>(Hhi, Hlo, outs[l], fo); break;
            case 256:
                attn_sep<128><<<dim3(2, N / 32), 256, smem_attn(128)>>>(Hhi, Hlo, outs[l], fo); break;
            case 128:
                attn_sep<128><<<dim3(1, N / 32), 256, smem_attn(128)>>>(Hhi, Hlo, outs[l], fo); break;
            case 64:
                attn_sep<64><<<dim3(1, N / 32), 256, smem_attn(64)>>>(Hhi, Hlo, outs[l], fo); break;
            case 16:
                attn_sep<16><<<dim3(1, N / 32), 256, smem_attn(16)>>>(Hhi, Hlo, outs[l], fo); break;
        }
    }
    (void)in_sizes; (void)n_in; (void)out_size;
}